// round 17
// baseline (speedup 1.0000x reference)
#include <cuda_runtime.h>
#include <cstdint>

#define VOCAB   50257
#define BATCH   512
#define SEQ     1024

// ---- launch 1 geometry ----
#define FILL_CTAS 1184                 // proven R5 fill config (8*148)
#define PREP_CTAS BATCH
#define THR       256
#define TOTAL_VEC ((BATCH * (size_t)VOCAB) / 4)   // exact: 6,432,896 float4

// pre-resolved scatter list (4MB total scratch)
__device__ unsigned int g_idx[BATCH * SEQ];   // global index b*VOCAB+tok
__device__ float        g_val[BATCH * SEQ];   // idf[tok] * inv_n[b]

__global__ void __launch_bounds__(THR, 8)
fused1_kernel(const void* __restrict__ xraw,
              const float* __restrict__ idf,
              float* __restrict__ out)
{
    const int bid = blockIdx.x;
    const int tid = threadIdx.x;

    if (bid < FILL_CTAS) {
        // ---------- role A: flat zero-fill (identical to R5's 10.5us fill) ----------
        const size_t stride = (size_t)FILL_CTAS * THR;
        const float4 z4 = make_float4(0.f, 0.f, 0.f, 0.f);
        #pragma unroll 4
        for (size_t i = (size_t)bid * THR + tid; i < TOTAL_VEC; i += stride)
            __stcs(&((float4*)out)[i], z4);
        return;
    }

    // ---------- role B: prep row b -> pre-resolved scatter list ----------
    const int b    = bid - FILL_CTAS;
    const int lane = tid & 31;
    const int wid  = tid >> 5;
    __shared__ float sh_part[THR / 32];
    __shared__ float sh_inv;

    // dtype detection, warp-local: int32 data read as u64 packs two tokens and
    // is >= VOCAB unless the odd one is 0; all-32-small prob ~ (1/50257)^32.
    const unsigned long long probe = ((const unsigned long long*)xraw)[lane];
    const int is64 = (__ballot_sync(0xffffffffu, probe >= (unsigned long long)VOCAB) == 0);

    // 4 tokens per thread, coalesced (t, t+256, t+512, t+768)
    const size_t base = (size_t)b * SEQ;
    int tok[4];
    float iv[4];
    #pragma unroll
    for (int k = 0; k < 4; ++k) {
        const size_t ix = base + tid + k * THR;
        tok[k] = is64 ? (int)((const long long*)xraw)[ix]
                      : ((const int*)xraw)[ix];
        iv[k] = __ldg(&idf[tok[k]]);
    }

    // n = sum idf[tok] over the row
    float w = iv[0] + iv[1] + iv[2] + iv[3];
    #pragma unroll
    for (int o = 16; o > 0; o >>= 1)
        w += __shfl_down_sync(0xffffffffu, w, o);
    if (lane == 0) sh_part[wid] = w;
    __syncthreads();
    if (wid == 0) {
        float v = (lane < THR / 32) ? sh_part[lane] : 0.0f;
        #pragma unroll
        for (int o = 4; o > 0; o >>= 1)
            v += __shfl_down_sync(0xffffffffu, v, o);
        if (lane == 0) sh_inv = 1.0f / v;
    }
    __syncthreads();
    const float inv_n = sh_inv;

    // emit pre-resolved (index, value) pairs, coalesced
    #pragma unroll
    for (int k = 0; k < 4; ++k) {
        const int i = b * SEQ + tid + k * THR;
        g_idx[i] = (unsigned int)((size_t)b * VOCAB + tok[k]);
        g_val[i] = iv[k] * inv_n;
    }
}

// ---------- launch 2: trivial scatter (coalesced loads + fire-and-forget RED) ----------
#define S2_CTAS 1024
#define S2_THR  256

__global__ void __launch_bounds__(S2_THR)
scatter2_kernel(float* __restrict__ out)
{
    const int i0 = blockIdx.x * (S2_THR * 2) + threadIdx.x;
    #pragma unroll
    for (int k = 0; k < 2; ++k) {
        const int i = i0 + k * S2_THR;
        const unsigned int idx = g_idx[i];
        const float        val = g_val[i];
        // duplicates of the same (b,tok) sum to count*idf*inv_n automatically
        atomicAdd(&out[idx], val);
    }
}

extern "C" void kernel_launch(void* const* d_in, const int* in_sizes, int n_in,
                              void* d_out, int out_size)
{
    const void*  x   = d_in[0];
    const float* idf = (const float*)d_in[1];
    float*       out = (float*)d_out;

    fused1_kernel<<<FILL_CTAS + PREP_CTAS, THR>>>(x, idf, out);
    scatter2_kernel<<<S2_CTAS, S2_THR>>>(out);
}